// round 8
// baseline (speedup 1.0000x reference)
#include <cuda_runtime.h>
#include <cuda_bf16.h>
#include <cuda_fp16.h>
#include <math.h>
#include <stdint.h>

#define B_   8
#define C1   128
#define C2   256
#define H_   80
#define W_   80
#define P_   6400
#define NPT  5

#define TPIX   128
#define KCH    64
#define NCHUNK 10

#define APITCH 144          // bytes per A row (64 fp16 = 128B + 16 pad)
#define BPITCH 144          // bytes per B row
#define OPITCH 132          // fp32 elements

// ---------------- device scratch ----------------
__device__ int4   g_idx[B_ * NPT * P_];
__device__ float4 g_gw [B_ * NPT * P_];
__device__ unsigned short g_wh[NCHUNK * C2 * KCH];   // fp16 weights [chunk][c2][64]
__device__ unsigned short g_xh[B_ * C1 * P_];        // fp16 mirror of x (13 MB)
__device__ float  g_pwT[C1 * 9 * 12];                // offset weights [c][tt][j pad12]

__device__ __forceinline__ uint32_t smem_u32(const void* p) {
    uint32_t a;
    asm("{ .reg .u64 t; cvta.to.shared.u64 t, %1; cvt.u32.u64 %0, t; }" : "=r"(a) : "l"(p));
    return a;
}

// r = {lo = f16(a), hi = f16(b)}
#define CVT2H(r, a, b) asm("cvt.rn.f16x2.f32 %0, %1, %2;" : "=r"(r) : "f"(b), "f"(a))

__device__ __forceinline__ float h2f(unsigned short u) {
    return __half2float(__ushort_as_half(u));
}

__device__ __forceinline__ void ldsm4(uint32_t* r, uint32_t addr) {
    asm volatile("ldmatrix.sync.aligned.m8n8.x4.shared.b16 {%0,%1,%2,%3}, [%4];"
        : "=r"(r[0]), "=r"(r[1]), "=r"(r[2]), "=r"(r[3]) : "r"(addr));
}

__device__ __forceinline__ void mma16816(float* d, const uint32_t* a, const uint32_t* b) {
    asm volatile("mma.sync.aligned.m16n8k16.row.col.f32.f16.f16.f32 "
        "{%0,%1,%2,%3}, {%4,%5,%6,%7}, {%8,%9}, {%0,%1,%2,%3};"
        : "+f"(d[0]), "+f"(d[1]), "+f"(d[2]), "+f"(d[3])
        : "r"(a[0]), "r"(a[1]), "r"(a[2]), "r"(a[3]), "r"(b[0]), "r"(b[1]));
}

// SMEM layout (bytes): BN | stage0 {A, B} | stage1 {A, B}
#define SM_BN    0
#define SM_ST    2048
#define A_BYTES  (TPIX * APITCH)         // 18432
#define B_BYTES  (C2 * BPITCH)           // 36864
#define STG      (A_BYTES + B_BYTES)     // 55296
#define SM_TOTAL (SM_ST + 2 * STG)       // 112640

// ---------------------------------------------------------------------------
__global__ void prep_kernel(const float* __restrict__ cw, const float* __restrict__ pw) {
    int e = blockIdx.x * 256 + threadIdx.x;
    if (e < NCHUNK * C2 * KCH) {
        int c   = e >> 14;
        int r   = e & 16383;
        int n   = r >> 6;
        int kk  = r & 63;
        int kpt = c >> 1;
        int c1  = (c & 1) * KCH + kk;
        float v = cw[(n * C1 + c1) * NPT + kpt];
        g_wh[e] = __half_as_ushort(__float2half(v));
    }
    if (e < C1 * 9 * 12) {
        int j  = e % 12;
        int ct = e / 12;
        int c  = ct / 9;
        int tt = ct % 9;
        g_pwT[e] = (j < 10) ? pw[(j * C1 + c) * 9 + tt] : 0.f;
    }
}

// ---------------------------------------------------------------------------
// offset conv (3x3, pad 1) + bilinear params; also emits fp16 mirror of x
// ---------------------------------------------------------------------------
__global__ __launch_bounds__(256)
void offset_kernel(const float* __restrict__ x, const float* __restrict__ pb) {
    extern __shared__ float sw[];
    int t = threadIdx.x;
    for (int i = t; i < C1 * 9 * 12; i += 256) sw[i] = g_pwT[i];
    __syncthreads();

    int tid = blockIdx.x * 256 + t;
    int b = tid / P_, p = tid % P_, h = p / W_, w = p % W_;

    float acc[10];
#pragma unroll
    for (int j = 0; j < 10; j++) acc[j] = pb[j];

    int off[9]; bool ok[9];
#pragma unroll
    for (int tt = 0; tt < 9; tt++) {
        int dh = tt / 3 - 1, dw = tt % 3 - 1;
        int hh = h + dh, ww = w + dw;
        ok[tt]  = (hh >= 0) && (hh < H_) && (ww >= 0) && (ww < W_);
        off[tt] = hh * W_ + ww;
    }

    const float* xb = x + (size_t)b * C1 * P_;
    unsigned short* xhb = g_xh + (size_t)b * C1 * P_ + p;
    for (int c = 0; c < C1; c++) {
        const float* xc = xb + c * P_;
        float v[9];
#pragma unroll
        for (int tt = 0; tt < 9; tt++) v[tt] = ok[tt] ? __ldg(xc + off[tt]) : 0.f;
        xhb[c * P_] = __half_as_ushort(__float2half(v[4]));   // fp16 mirror (center tap)
        const float* wc = sw + c * 108;
#pragma unroll
        for (int tt = 0; tt < 9; tt++) {
            float4 w0 = *(const float4*)(wc + tt * 12);
            float4 w1 = *(const float4*)(wc + tt * 12 + 4);
            float2 w2 = *(const float2*)(wc + tt * 12 + 8);
            float xv = v[tt];
            acc[0] = fmaf(xv, w0.x, acc[0]); acc[1] = fmaf(xv, w0.y, acc[1]);
            acc[2] = fmaf(xv, w0.z, acc[2]); acc[3] = fmaf(xv, w0.w, acc[3]);
            acc[4] = fmaf(xv, w1.x, acc[4]); acc[5] = fmaf(xv, w1.y, acc[5]);
            acc[6] = fmaf(xv, w1.z, acc[6]); acc[7] = fmaf(xv, w1.w, acc[7]);
            acc[8] = fmaf(xv, w2.x, acc[8]); acc[9] = fmaf(xv, w2.y, acc[9]);
        }
    }

    const float pnx[NPT] = {0.f, 0.f, 1.f, 1.f, 2.f};
    const float pny[NPT] = {0.f, 1.f, 0.f, 1.f, 0.f};

#pragma unroll
    for (int k = 0; k < NPT; k++) {
        float px = acc[k]       + (float)h + pnx[k];
        float py = acc[NPT + k] + (float)w + pny[k];
        float pf = floorf(px), qf = floorf(py);
        float xl = fminf(fmaxf(pf,       0.f), (float)(H_ - 1));
        float yl = fminf(fmaxf(qf,       0.f), (float)(W_ - 1));
        float xr = fminf(fmaxf(pf + 1.f, 0.f), (float)(H_ - 1));
        float yr = fminf(fmaxf(qf + 1.f, 0.f), (float)(W_ - 1));
        float pxc = fminf(fmaxf(px, 0.f), (float)(H_ - 1));
        float pyc = fminf(fmaxf(py, 0.f), (float)(W_ - 1));
        float ax = 1.f + xl - pxc;
        float bx = 1.f - xr + pxc;
        float ay = 1.f + yl - pyc;
        float by = 1.f - yr + pyc;
        int ixl = (int)xl, iyl = (int)yl, ixr = (int)xr, iyr = (int)yr;
        int gi = (b * NPT + k) * P_ + p;
        g_idx[gi] = make_int4(ixl * W_ + iyl, ixr * W_ + iyr,
                              ixl * W_ + iyr, ixr * W_ + iyl);
        g_gw[gi]  = make_float4(ax * ay, bx * by, ax * by, bx * ay);
    }
}

// 8 corner loads (fp16) for sample row-pair s
#define LOADS(dst, s_) do {                                                   \
    const unsigned short* r0_ = xcb + (size_t)(2 * (s_)) * P_;                \
    const unsigned short* r1_ = r0_ + P_;                                     \
    (dst)[0] = __ldg(r0_ + id.x); (dst)[1] = __ldg(r0_ + id.y);               \
    (dst)[2] = __ldg(r0_ + id.z); (dst)[3] = __ldg(r0_ + id.w);               \
    (dst)[4] = __ldg(r1_ + id.x); (dst)[5] = __ldg(r1_ + id.y);               \
    (dst)[6] = __ldg(r1_ + id.z); (dst)[7] = __ldg(r1_ + id.w);               \
} while (0)

// ---------------------------------------------------------------------------
// main: pipelined fp16 gather + mma.sync + BN/SiLU
// CTA 128 pixels x 256 c2, 512 threads, double-buffered K chunks of 64.
// ---------------------------------------------------------------------------
__global__ __launch_bounds__(512, 1)
void main_kernel(const float* __restrict__ bng, const float* __restrict__ bnb,
                 const float* __restrict__ bnm, const float* __restrict__ bnv,
                 float* __restrict__ out) {
    extern __shared__ char smem[];
    uint32_t sb = smem_u32(smem);
    int t = threadIdx.x, wid = t >> 5, lid = t & 31;
    int b = blockIdx.y;
    int p0 = blockIdx.x * TPIX;

    if (t < 256) {
        float sc = bng[t] * rsqrtf(bnv[t] + 1e-5f);
        ((float*)(smem + SM_BN))[t]       = sc;
        ((float*)(smem + SM_BN))[256 + t] = bnb[t] - bnm[t] * sc;
    }

    int pix = t & 127;          // gather: pixel
    int kg  = t >> 7;           // gather: 16-c1 group (0..3)
    int wm  = wid & 3;
    int wn  = wid >> 2;
    const unsigned short* xhb = g_xh + (size_t)b * C1 * P_;

    float acc[2][8][4];
#pragma unroll
    for (int mt = 0; mt < 2; mt++)
#pragma unroll
        for (int nt = 0; nt < 8; nt++)
#pragma unroll
            for (int j = 0; j < 4; j++) acc[mt][nt][j] = 0.f;

    // ---- prologue: stage chunk 0 into stage 0 ----
    {
        const uint4* src = (const uint4*)g_wh;
#pragma unroll
        for (int i = 0; i < 4; i++) {
            int u = i * 512 + t;
            *(uint4*)(smem + SM_ST + A_BYTES + (u >> 3) * BPITCH + (u & 7) * 16) =
                __ldg(src + u);
        }
        int gi = b * NPT * P_ + p0 + pix;
        int4   id  = __ldg(&g_idx[gi]);
        float4 gwv = __ldg(&g_gw[gi]);
        const unsigned short* xcb = xhb + (size_t)(kg * 16) * P_;
#pragma unroll
        for (int i = 0; i < 8; i++) {
            unsigned short cb[8];
            LOADS(cb, i);
            float v0 = gwv.x * h2f(cb[0]) + gwv.y * h2f(cb[1])
                     + gwv.z * h2f(cb[2]) + gwv.w * h2f(cb[3]);
            float v1 = gwv.x * h2f(cb[4]) + gwv.y * h2f(cb[5])
                     + gwv.z * h2f(cb[6]) + gwv.w * h2f(cb[7]);
            unsigned h; CVT2H(h, v0, v1);
            *(unsigned*)(smem + SM_ST + (uint32_t)pix * APITCH + kg * 32 + i * 4) = h;
        }
    }
    __syncthreads();

#pragma unroll 1
    for (int c = 0; c < NCHUNK; c++) {
        int st = c & 1;
        uint32_t sA  = sb + SM_ST + st * STG;
        uint32_t sBB = sA + A_BYTES;
        uint32_t nA  = SM_ST + (st ^ 1) * STG;
        bool pf = (c < NCHUNK - 1);
        int cn = c + 1;

        // prefetch next B tile + bilinear params; preload 2 s-iterations of corners
        uint4 breg[4];
        int4 id; float4 gwv;
        const unsigned short* xcb = xhb;
        unsigned short cb[2][8];
        if (pf) {
            const uint4* src = (const uint4*)(g_wh + cn * C2 * KCH);
#pragma unroll
            for (int i = 0; i < 4; i++) breg[i] = __ldg(src + i * 512 + t);
            int gi = (b * NPT + (cn >> 1)) * P_ + p0 + pix;
            id  = __ldg(&g_idx[gi]);
            gwv = __ldg(&g_gw[gi]);
            xcb = xhb + (size_t)((cn & 1) * KCH + kg * 16) * P_;
            LOADS(cb[0], 0);
            LOADS(cb[1], 1);
        }

        uint32_t aA = sA + (wm * 32 + (lid & 15)) * APITCH + (lid >> 4) * 16;
        uint32_t aB = sBB + (wn * 64 + (lid & 7) + (lid >> 4) * 8) * BPITCH
                    + ((lid >> 3) & 1) * 16;
        uint32_t dA = nA + (uint32_t)pix * APITCH + kg * 32;

        uint32_t ah[2][4];
#pragma unroll
        for (int s = 0; s < 8; s++) {
            int ks = s >> 1, gp = s & 1;

            if (gp == 0) {
                ldsm4(ah[0], aA + ks * 32);
                ldsm4(ah[1], aA + 16 * APITCH + ks * 32);
            }

            // combine corners loaded 2 iterations ago; refill the buffer
            if (pf) {
                unsigned short* cs = cb[s & 1];
                float v0 = gwv.x * h2f(cs[0]) + gwv.y * h2f(cs[1])
                         + gwv.z * h2f(cs[2]) + gwv.w * h2f(cs[3]);
                float v1 = gwv.x * h2f(cs[4]) + gwv.y * h2f(cs[5])
                         + gwv.z * h2f(cs[6]) + gwv.w * h2f(cs[7]);
                unsigned h; CVT2H(h, v0, v1);
                *(unsigned*)(smem + dA + s * 4) = h;
                if (s < 6) LOADS(cs, s + 2);
            }

#pragma unroll
            for (int g2 = 0; g2 < 2; g2++) {
                int g = gp * 2 + g2;
                uint32_t bf[4];
                ldsm4(bf, aB + g * 16 * BPITCH + ks * 32);
#pragma unroll
                for (int mt = 0; mt < 2; mt++) {
                    mma16816(acc[mt][2 * g],     ah[mt], bf);
                    mma16816(acc[mt][2 * g + 1], ah[mt], bf + 2);
                }
            }
        }

        if (pf) {
#pragma unroll
            for (int i = 0; i < 4; i++) {
                int u = i * 512 + t;
                *(uint4*)(smem + nA + A_BYTES + (u >> 3) * BPITCH + (u & 7) * 16) =
                    breg[i];
            }
        }
        __syncthreads();
    }

    // ---- epilogue: BN + SiLU via SMEM transpose, coalesced out ----
    const float* scs = (const float*)(smem + SM_BN);
    const float* shs = scs + 256;
    float* sO = (float*)(smem + SM_ST);
#pragma unroll
    for (int half = 0; half < 2; half++) {
        if ((wn >> 1) == half) {
#pragma unroll
            for (int mt = 0; mt < 2; mt++)
#pragma unroll
                for (int nt = 0; nt < 8; nt++)
#pragma unroll
                    for (int j = 0; j < 4; j++) {
                        int row = wm * 32 + mt * 16 + (lid >> 2) + 8 * (j >> 1);
                        int col = (wn & 1) * 64 + nt * 8 + 2 * (lid & 3) + (j & 1);
                        sO[col * OPITCH + row] = acc[mt][nt][j];
                    }
        }
        __syncthreads();
#pragma unroll
        for (int it = 0; it < 32; it++) {
            int idx = it * 512 + t;
            int c2l = idx >> 7, pp = idx & 127;
            int c2 = half * 128 + c2l;
            float v = sO[c2l * OPITCH + pp] * scs[c2] + shs[c2];
            out[((size_t)b * C2 + c2) * P_ + p0 + pp] = v / (1.f + __expf(-v));
        }
        __syncthreads();
    }
}

// ---------------------------------------------------------------------------
extern "C" void kernel_launch(void* const* d_in, const int* in_sizes, int n_in,
                              void* d_out, int out_size) {
    const float* x   = (const float*)d_in[0];
    const float* pw  = (const float*)d_in[1];
    const float* pb  = (const float*)d_in[2];
    const float* cw  = (const float*)d_in[3];
    const float* bng = (const float*)d_in[4];
    const float* bnb = (const float*)d_in[5];
    const float* bnm = (const float*)d_in[6];
    const float* bnv = (const float*)d_in[7];
    float* out = (float*)d_out;

    cudaFuncSetAttribute(offset_kernel, cudaFuncAttributeMaxDynamicSharedMemorySize, 55296);
    cudaFuncSetAttribute(main_kernel,   cudaFuncAttributeMaxDynamicSharedMemorySize, SM_TOTAL);

    prep_kernel<<<(NCHUNK * C2 * KCH + 255) / 256, 256>>>(cw, pw);
    offset_kernel<<<B_ * P_ / 256, 256, 55296>>>(x, pb);
    dim3 g2(P_ / TPIX, B_);
    main_kernel<<<g2, 512, SM_TOTAL>>>(bng, bnb, bnm, bnv, out);
}

// round 10
// speedup vs baseline: 1.2125x; 1.2125x over previous
#include <cuda_runtime.h>
#include <cuda_bf16.h>
#include <cuda_fp16.h>
#include <math.h>
#include <stdint.h>

#define B_   8
#define C1   128
#define C2   256
#define H_   80
#define W_   80
#define P_   6400
#define NPT  5

#define TPIX   128
#define KCH    64
#define NCHUNK 10

#define APITCH 144          // bytes per A row (64 fp16 = 128B + 16 pad)
#define BPITCH 144          // bytes per B row
#define OPITCH 132          // fp32 elements

// ---------------- device scratch ----------------
__device__ int4   g_idx[B_ * NPT * P_];
__device__ float4 g_gw [B_ * NPT * P_];
__device__ unsigned short g_wh[NCHUNK * C2 * KCH];   // fp16 weights [chunk][c2][64]
__device__ uint32_t g_x2[B_ * (C1 / 2) * P_];        // fp16x2 channel-paired x (13 MB)
__device__ float  g_pwT[C1 * 9 * 12];                // offset weights [c][tt][j pad12]

__device__ __forceinline__ uint32_t smem_u32(const void* p) {
    uint32_t a;
    asm("{ .reg .u64 t; cvta.to.shared.u64 t, %1; cvt.u32.u64 %0, t; }" : "=r"(a) : "l"(p));
    return a;
}

// r = {lo = f16(a), hi = f16(b)}
#define CVT2H(r, a, b) asm("cvt.rn.f16x2.f32 %0, %1, %2;" : "=r"(r) : "f"(b), "f"(a))

__device__ __forceinline__ float2 up2(uint32_t u) {
    return __half22float2(*(const __half2*)&u);
}

__device__ __forceinline__ void ldsm4(uint32_t* r, uint32_t addr) {
    asm volatile("ldmatrix.sync.aligned.m8n8.x4.shared.b16 {%0,%1,%2,%3}, [%4];"
        : "=r"(r[0]), "=r"(r[1]), "=r"(r[2]), "=r"(r[3]) : "r"(addr));
}

__device__ __forceinline__ void mma16816(float* d, const uint32_t* a, const uint32_t* b) {
    asm volatile("mma.sync.aligned.m16n8k16.row.col.f32.f16.f16.f32 "
        "{%0,%1,%2,%3}, {%4,%5,%6,%7}, {%8,%9}, {%0,%1,%2,%3};"
        : "+f"(d[0]), "+f"(d[1]), "+f"(d[2]), "+f"(d[3])
        : "r"(a[0]), "r"(a[1]), "r"(a[2]), "r"(a[3]), "r"(b[0]), "r"(b[1]));
}

// SMEM layout (bytes): BN | stage0 {A, B} | stage1 {A, B}
#define SM_BN    0
#define SM_ST    2048
#define A_BYTES  (TPIX * APITCH)         // 18432
#define B_BYTES  (C2 * BPITCH)           // 36864
#define STG      (A_BYTES + B_BYTES)     // 55296
#define SM_TOTAL (SM_ST + 2 * STG)       // 112640

// ---------------------------------------------------------------------------
__global__ void prep_kernel(const float* __restrict__ cw, const float* __restrict__ pw) {
    int e = blockIdx.x * 256 + threadIdx.x;
    if (e < NCHUNK * C2 * KCH) {
        int c   = e >> 14;
        int r   = e & 16383;
        int n   = r >> 6;
        int kk  = r & 63;
        int kpt = c >> 1;
        int c1  = (c & 1) * KCH + kk;
        float v = cw[(n * C1 + c1) * NPT + kpt];
        g_wh[e] = __half_as_ushort(__float2half(v));
    }
    if (e < C1 * 9 * 12) {
        int j  = e % 12;
        int ct = e / 12;
        int c  = ct / 9;
        int tt = ct % 9;
        g_pwT[e] = (j < 10) ? pw[(j * C1 + c) * 9 + tt] : 0.f;
    }
}

// ---------------------------------------------------------------------------
// offset conv (3x3, pad 1) + bilinear params; also emits fp16x2 paired mirror
// ---------------------------------------------------------------------------
__global__ __launch_bounds__(256)
void offset_kernel(const float* __restrict__ x, const float* __restrict__ pb) {
    extern __shared__ float sw[];
    int t = threadIdx.x;
    for (int i = t; i < C1 * 9 * 12; i += 256) sw[i] = g_pwT[i];
    __syncthreads();

    int tid = blockIdx.x * 256 + t;
    int b = tid / P_, p = tid % P_, h = p / W_, w = p % W_;

    float acc[10];
#pragma unroll
    for (int j = 0; j < 10; j++) acc[j] = pb[j];

    int off[9]; bool ok[9];
#pragma unroll
    for (int tt = 0; tt < 9; tt++) {
        int dh = tt / 3 - 1, dw = tt % 3 - 1;
        int hh = h + dh, ww = w + dw;
        ok[tt]  = (hh >= 0) && (hh < H_) && (ww >= 0) && (ww < W_);
        off[tt] = hh * W_ + ww;
    }

    const float* xb = x + (size_t)b * C1 * P_;
    // fp16 mirror: halfword index = ((b*64 + c/2)*P_ + p)*2 + (c&1)
    unsigned short* xq = (unsigned short*)g_x2 + ((size_t)b * 64 * P_ + p) * 2;
    for (int c = 0; c < C1; c++) {
        const float* xc = xb + c * P_;
        float v[9];
#pragma unroll
        for (int tt = 0; tt < 9; tt++) v[tt] = ok[tt] ? __ldg(xc + off[tt]) : 0.f;
        xq[(size_t)(c >> 1) * P_ * 2 + (c & 1)] = __half_as_ushort(__float2half(v[4]));
        const float* wc = sw + c * 108;
#pragma unroll
        for (int tt = 0; tt < 9; tt++) {
            float4 w0 = *(const float4*)(wc + tt * 12);
            float4 w1 = *(const float4*)(wc + tt * 12 + 4);
            float2 w2 = *(const float2*)(wc + tt * 12 + 8);
            float xv = v[tt];
            acc[0] = fmaf(xv, w0.x, acc[0]); acc[1] = fmaf(xv, w0.y, acc[1]);
            acc[2] = fmaf(xv, w0.z, acc[2]); acc[3] = fmaf(xv, w0.w, acc[3]);
            acc[4] = fmaf(xv, w1.x, acc[4]); acc[5] = fmaf(xv, w1.y, acc[5]);
            acc[6] = fmaf(xv, w1.z, acc[6]); acc[7] = fmaf(xv, w1.w, acc[7]);
            acc[8] = fmaf(xv, w2.x, acc[8]); acc[9] = fmaf(xv, w2.y, acc[9]);
        }
    }

    const float pnx[NPT] = {0.f, 0.f, 1.f, 1.f, 2.f};
    const float pny[NPT] = {0.f, 1.f, 0.f, 1.f, 0.f};

#pragma unroll
    for (int k = 0; k < NPT; k++) {
        float px = acc[k]       + (float)h + pnx[k];
        float py = acc[NPT + k] + (float)w + pny[k];
        float pf = floorf(px), qf = floorf(py);
        float xl = fminf(fmaxf(pf,       0.f), (float)(H_ - 1));
        float yl = fminf(fmaxf(qf,       0.f), (float)(W_ - 1));
        float xr = fminf(fmaxf(pf + 1.f, 0.f), (float)(H_ - 1));
        float yr = fminf(fmaxf(qf + 1.f, 0.f), (float)(W_ - 1));
        float pxc = fminf(fmaxf(px, 0.f), (float)(H_ - 1));
        float pyc = fminf(fmaxf(py, 0.f), (float)(W_ - 1));
        float ax = 1.f + xl - pxc;
        float bx = 1.f - xr + pxc;
        float ay = 1.f + yl - pyc;
        float by = 1.f - yr + pyc;
        int ixl = (int)xl, iyl = (int)yl, ixr = (int)xr, iyr = (int)yr;
        int gi = (b * NPT + k) * P_ + p;
        g_idx[gi] = make_int4(ixl * W_ + iyl, ixr * W_ + iyr,
                              ixl * W_ + iyr, ixr * W_ + iyl);
        g_gw[gi]  = make_float4(ax * ay, bx * by, ax * by, bx * ay);
    }
}

// ---------------------------------------------------------------------------
// main: R7 structure, gather via fp16x2 paired mirror (4 loads per pair)
// CTA 128 pixels x 256 c2, 512 threads, double-buffered K chunks of 64.
// ---------------------------------------------------------------------------
__global__ __launch_bounds__(512, 1)
void main_kernel(const float* __restrict__ bng, const float* __restrict__ bnb,
                 const float* __restrict__ bnm, const float* __restrict__ bnv,
                 float* __restrict__ out) {
    extern __shared__ char smem[];
    uint32_t sb = smem_u32(smem);
    int t = threadIdx.x, wid = t >> 5, lid = t & 31;
    int b = blockIdx.y;
    int p0 = blockIdx.x * TPIX;

    if (t < 256) {
        float sc = bng[t] * rsqrtf(bnv[t] + 1e-5f);
        ((float*)(smem + SM_BN))[t]       = sc;
        ((float*)(smem + SM_BN))[256 + t] = bnb[t] - bnm[t] * sc;
    }

    int pix = t & 127;          // gather: pixel
    int kg  = t >> 7;           // gather: 8-pair group (0..3)
    int wm  = wid & 3;
    int wn  = wid >> 2;
    const uint32_t* x2b = g_x2 + (size_t)b * 64 * P_;

    float acc[2][8][4];
#pragma unroll
    for (int mt = 0; mt < 2; mt++)
#pragma unroll
        for (int nt = 0; nt < 8; nt++)
#pragma unroll
            for (int j = 0; j < 4; j++) acc[mt][nt][j] = 0.f;

    // ---- prologue: stage chunk 0 into stage 0 ----
    {
        const uint4* src = (const uint4*)g_wh;
#pragma unroll
        for (int i = 0; i < 4; i++) {
            int u = i * 512 + t;
            *(uint4*)(smem + SM_ST + A_BYTES + (u >> 3) * BPITCH + (u & 7) * 16) =
                __ldg(src + u);
        }
        int gi = b * NPT * P_ + p0 + pix;
        int4   id  = __ldg(&g_idx[gi]);
        float4 gwv = __ldg(&g_gw[gi]);
        const uint32_t* xc = x2b + (size_t)(kg * 8) * P_;
#pragma unroll
        for (int i = 0; i < 8; i++) {
            const uint32_t* xp = xc + (size_t)i * P_;
            float2 f0 = up2(__ldg(xp + id.x));
            float2 f1 = up2(__ldg(xp + id.y));
            float2 f2 = up2(__ldg(xp + id.z));
            float2 f3 = up2(__ldg(xp + id.w));
            float v0 = gwv.x * f0.x + gwv.y * f1.x + gwv.z * f2.x + gwv.w * f3.x;
            float v1 = gwv.x * f0.y + gwv.y * f1.y + gwv.z * f2.y + gwv.w * f3.y;
            unsigned h; CVT2H(h, v0, v1);
            *(unsigned*)(smem + SM_ST + (uint32_t)pix * APITCH + kg * 32 + i * 4) = h;
        }
    }
    __syncthreads();

#pragma unroll 1
    for (int c = 0; c < NCHUNK; c++) {
        int st = c & 1;
        uint32_t sA  = sb + SM_ST + st * STG;
        uint32_t sBB = sA + A_BYTES;
        uint32_t nA  = SM_ST + (st ^ 1) * STG;
        bool pf = (c < NCHUNK - 1);
        int cn = c + 1;

        // prefetch next B tile + bilinear params
        uint4 breg[4];
        int4 id; float4 gwv;
        const uint32_t* xc = x2b;
        if (pf) {
            const uint4* src = (const uint4*)(g_wh + cn * C2 * KCH);
#pragma unroll
            for (int i = 0; i < 4; i++) breg[i] = __ldg(src + i * 512 + t);
            int gi = (b * NPT + (cn >> 1)) * P_ + p0 + pix;
            id  = __ldg(&g_idx[gi]);
            gwv = __ldg(&g_gw[gi]);
            xc = x2b + (size_t)((cn & 1) * 32 + kg * 8) * P_;
        }

        uint32_t aA = sA + (wm * 32 + (lid & 15)) * APITCH + (lid >> 4) * 16;
        uint32_t aB = sBB + (wn * 64 + (lid & 7) + (lid >> 4) * 8) * BPITCH
                    + ((lid >> 3) & 1) * 16;
        uint32_t dA = nA + (uint32_t)pix * APITCH + kg * 32;

        uint32_t ah[2][4];
#pragma unroll
        for (int s = 0; s < 8; s++) {
            int ks = s >> 1, gp = s & 1;

            // issue next-chunk corner loads (1 c1-pair) early
            uint32_t u0, u1, u2, u3;
            if (pf) {
                const uint32_t* xp = xc + (size_t)s * P_;
                u0 = __ldg(xp + id.x); u1 = __ldg(xp + id.y);
                u2 = __ldg(xp + id.z); u3 = __ldg(xp + id.w);
            }

            if (gp == 0) {
                ldsm4(ah[0], aA + ks * 32);
                ldsm4(ah[1], aA + 16 * APITCH + ks * 32);
            }

#pragma unroll
            for (int g2 = 0; g2 < 2; g2++) {
                int g = gp * 2 + g2;
                uint32_t bf[4];
                ldsm4(bf, aB + g * 16 * BPITCH + ks * 32);
#pragma unroll
                for (int mt = 0; mt < 2; mt++) {
                    mma16816(acc[mt][2 * g],     ah[mt], bf);
                    mma16816(acc[mt][2 * g + 1], ah[mt], bf + 2);
                }
            }

            // combine + convert + store the pair
            if (pf) {
                float2 f0 = up2(u0), f1 = up2(u1), f2 = up2(u2), f3 = up2(u3);
                float v0 = gwv.x * f0.x + gwv.y * f1.x + gwv.z * f2.x + gwv.w * f3.x;
                float v1 = gwv.x * f0.y + gwv.y * f1.y + gwv.z * f2.y + gwv.w * f3.y;
                unsigned h; CVT2H(h, v0, v1);
                *(unsigned*)(smem + dA + s * 4) = h;
            }
        }

        if (pf) {
#pragma unroll
            for (int i = 0; i < 4; i++) {
                int u = i * 512 + t;
                *(uint4*)(smem + nA + A_BYTES + (u >> 3) * BPITCH + (u & 7) * 16) =
                    breg[i];
            }
        }
        __syncthreads();
    }

    // ---- epilogue: BN + SiLU via SMEM transpose, coalesced out ----
    const float* scs = (const float*)(smem + SM_BN);
    const float* shs = scs + 256;
    float* sO = (float*)(smem + SM_ST);
#pragma unroll
    for (int half = 0; half < 2; half++) {
        if ((wn >> 1) == half) {
#pragma unroll
            for (int mt = 0; mt < 2; mt++)
#pragma unroll
                for (int nt = 0; nt < 8; nt++)
#pragma unroll
                    for (int j = 0; j < 4; j++) {
                        int row = wm * 32 + mt * 16 + (lid >> 2) + 8 * (j >> 1);
                        int col = (wn & 1) * 64 + nt * 8 + 2 * (lid & 3) + (j & 1);
                        sO[col * OPITCH + row] = acc[mt][nt][j];
                    }
        }
        __syncthreads();
#pragma unroll
        for (int it = 0; it < 32; it++) {
            int idx = it * 512 + t;
            int c2l = idx >> 7, pp = idx & 127;
            int c2 = half * 128 + c2l;
            float v = sO[c2l * OPITCH + pp] * scs[c2] + shs[c2];
            out[((size_t)b * C2 + c2) * P_ + p0 + pp] = v / (1.f + __expf(-v));
        }
        __syncthreads();
    }
}

// ---------------------------------------------------------------------------
extern "C" void kernel_launch(void* const* d_in, const int* in_sizes, int n_in,
                              void* d_out, int out_size) {
    const float* x   = (const float*)d_in[0];
    const float* pw  = (const float*)d_in[1];
    const float* pb  = (const float*)d_in[2];
    const float* cw  = (const float*)d_in[3];
    const float* bng = (const float*)d_in[4];
    const float* bnb = (const float*)d_in[5];
    const float* bnm = (const float*)d_in[6];
    const float* bnv = (const float*)d_in[7];
    float* out = (float*)d_out;

    cudaFuncSetAttribute(offset_kernel, cudaFuncAttributeMaxDynamicSharedMemorySize, 55296);
    cudaFuncSetAttribute(main_kernel,   cudaFuncAttributeMaxDynamicSharedMemorySize, SM_TOTAL);

    prep_kernel<<<(NCHUNK * C2 * KCH + 255) / 256, 256>>>(cw, pw);
    offset_kernel<<<B_ * P_ / 256, 256, 55296>>>(x, pb);
    dim3 g2(P_ / TPIX, B_);
    main_kernel<<<g2, 512, SM_TOTAL>>>(bng, bnb, bnm, bnv, out);
}

// round 12
// speedup vs baseline: 1.2135x; 1.0009x over previous
#include <cuda_runtime.h>
#include <cuda_bf16.h>
#include <cuda_fp16.h>
#include <math.h>
#include <stdint.h>

#define B_   8
#define C1   128
#define C2   256
#define H_   80
#define W_   80
#define P_   6400
#define NPT  5

#define TPIX   128
#define KCH    64
#define NCHUNK 10

#define APITCH 144          // bytes per A row (64 fp16 = 128B + 16 pad)
#define BPITCH 144          // bytes per B row
#define OPITCH 132          // fp32 elements

// ---------------- device scratch ----------------
__device__ int4   g_idx[B_ * NPT * P_];
__device__ float4 g_gw [B_ * NPT * P_];
__device__ unsigned short g_wh[NCHUNK * C2 * KCH];   // fp16 weights [chunk][c2][64]
__device__ uint32_t g_x2[B_ * (C1 / 2) * P_];        // fp16x2 channel-paired x (13 MB)
__device__ float  g_pwT[C1 * 9 * 12];                // offset weights [c][tt][j pad12]

__device__ __forceinline__ uint32_t smem_u32(const void* p) {
    uint32_t a;
    asm("{ .reg .u64 t; cvta.to.shared.u64 t, %1; cvt.u32.u64 %0, t; }" : "=r"(a) : "l"(p));
    return a;
}

// r = {lo = f16(a), hi = f16(b)}
#define CVT2H(r, a, b) asm("cvt.rn.f16x2.f32 %0, %1, %2;" : "=r"(r) : "f"(b), "f"(a))

__device__ __forceinline__ float2 up2(uint32_t u) {
    return __half22float2(*(const __half2*)&u);
}

__device__ __forceinline__ void ldsm4(uint32_t* r, uint32_t addr) {
    asm volatile("ldmatrix.sync.aligned.m8n8.x4.shared.b16 {%0,%1,%2,%3}, [%4];"
        : "=r"(r[0]), "=r"(r[1]), "=r"(r[2]), "=r"(r[3]) : "r"(addr));
}

__device__ __forceinline__ void mma16816(float* d, const uint32_t* a, const uint32_t* b) {
    asm volatile("mma.sync.aligned.m16n8k16.row.col.f32.f16.f16.f32 "
        "{%0,%1,%2,%3}, {%4,%5,%6,%7}, {%8,%9}, {%0,%1,%2,%3};"
        : "+f"(d[0]), "+f"(d[1]), "+f"(d[2]), "+f"(d[3])
        : "r"(a[0]), "r"(a[1]), "r"(a[2]), "r"(a[3]), "r"(b[0]), "r"(b[1]));
}

// SMEM layout (bytes): BN | stage0 {A, B} | stage1 {A, B}
#define SM_BN    0
#define SM_ST    2048
#define A_BYTES  (TPIX * APITCH)         // 18432
#define B_BYTES  (C2 * BPITCH)           // 36864
#define STG      (A_BYTES + B_BYTES)     // 55296
#define SM_TOTAL (SM_ST + 2 * STG)       // 112640

// ---------------------------------------------------------------------------
__global__ void prep_kernel(const float* __restrict__ cw, const float* __restrict__ pw) {
    int e = blockIdx.x * 256 + threadIdx.x;
    if (e < NCHUNK * C2 * KCH) {
        int c   = e >> 14;
        int r   = e & 16383;
        int n   = r >> 6;
        int kk  = r & 63;
        int kpt = c >> 1;
        int c1  = (c & 1) * KCH + kk;
        float v = cw[(n * C1 + c1) * NPT + kpt];
        g_wh[e] = __half_as_ushort(__float2half(v));
    }
    if (e < C1 * 9 * 12) {
        int j  = e % 12;
        int ct = e / 12;
        int c  = ct / 9;
        int tt = ct % 9;
        g_pwT[e] = (j < 10) ? pw[(j * C1 + c) * 9 + tt] : 0.f;
    }
}

// ---------------------------------------------------------------------------
// offset conv (3x3, pad 1) + bilinear params; also emits fp16x2 paired mirror
// ---------------------------------------------------------------------------
__global__ __launch_bounds__(256)
void offset_kernel(const float* __restrict__ x, const float* __restrict__ pb) {
    extern __shared__ float sw[];
    int t = threadIdx.x;
    for (int i = t; i < C1 * 9 * 12; i += 256) sw[i] = g_pwT[i];
    __syncthreads();

    int tid = blockIdx.x * 256 + t;
    int b = tid / P_, p = tid % P_, h = p / W_, w = p % W_;

    float acc[10];
#pragma unroll
    for (int j = 0; j < 10; j++) acc[j] = pb[j];

    int off[9]; bool ok[9];
#pragma unroll
    for (int tt = 0; tt < 9; tt++) {
        int dh = tt / 3 - 1, dw = tt % 3 - 1;
        int hh = h + dh, ww = w + dw;
        ok[tt]  = (hh >= 0) && (hh < H_) && (ww >= 0) && (ww < W_);
        off[tt] = hh * W_ + ww;
    }

    const float* xb = x + (size_t)b * C1 * P_;
    // fp16 mirror: halfword index = ((b*64 + c/2)*P_ + p)*2 + (c&1)
    unsigned short* xq = (unsigned short*)g_x2 + ((size_t)b * 64 * P_ + p) * 2;
    for (int c = 0; c < C1; c++) {
        const float* xc = xb + c * P_;
        float v[9];
#pragma unroll
        for (int tt = 0; tt < 9; tt++) v[tt] = ok[tt] ? __ldg(xc + off[tt]) : 0.f;
        xq[(size_t)(c >> 1) * P_ * 2 + (c & 1)] = __half_as_ushort(__float2half(v[4]));
        const float* wc = sw + c * 108;
#pragma unroll
        for (int tt = 0; tt < 9; tt++) {
            float4 w0 = *(const float4*)(wc + tt * 12);
            float4 w1 = *(const float4*)(wc + tt * 12 + 4);
            float2 w2 = *(const float2*)(wc + tt * 12 + 8);
            float xv = v[tt];
            acc[0] = fmaf(xv, w0.x, acc[0]); acc[1] = fmaf(xv, w0.y, acc[1]);
            acc[2] = fmaf(xv, w0.z, acc[2]); acc[3] = fmaf(xv, w0.w, acc[3]);
            acc[4] = fmaf(xv, w1.x, acc[4]); acc[5] = fmaf(xv, w1.y, acc[5]);
            acc[6] = fmaf(xv, w1.z, acc[6]); acc[7] = fmaf(xv, w1.w, acc[7]);
            acc[8] = fmaf(xv, w2.x, acc[8]); acc[9] = fmaf(xv, w2.y, acc[9]);
        }
    }

    const float pnx[NPT] = {0.f, 0.f, 1.f, 1.f, 2.f};
    const float pny[NPT] = {0.f, 1.f, 0.f, 1.f, 0.f};

#pragma unroll
    for (int k = 0; k < NPT; k++) {
        float px = acc[k]       + (float)h + pnx[k];
        float py = acc[NPT + k] + (float)w + pny[k];
        float pf = floorf(px), qf = floorf(py);
        float xl = fminf(fmaxf(pf,       0.f), (float)(H_ - 1));
        float yl = fminf(fmaxf(qf,       0.f), (float)(W_ - 1));
        float xr = fminf(fmaxf(pf + 1.f, 0.f), (float)(H_ - 1));
        float yr = fminf(fmaxf(qf + 1.f, 0.f), (float)(W_ - 1));
        float pxc = fminf(fmaxf(px, 0.f), (float)(H_ - 1));
        float pyc = fminf(fmaxf(py, 0.f), (float)(W_ - 1));
        float ax = 1.f + xl - pxc;
        float bx = 1.f - xr + pxc;
        float ay = 1.f + yl - pyc;
        float by = 1.f - yr + pyc;
        int ixl = (int)xl, iyl = (int)yl, ixr = (int)xr, iyr = (int)yr;
        int gi = (b * NPT + k) * P_ + p;
        g_idx[gi] = make_int4(ixl * W_ + iyl, ixr * W_ + iyr,
                              ixl * W_ + iyr, ixr * W_ + iyl);
        g_gw[gi]  = make_float4(ax * ay, bx * by, ax * by, bx * ay);
    }
}

// ---------------------------------------------------------------------------
// main: R10 structure + 2-deep corner-load pipeline (issue s+1, consume s)
// CTA 128 pixels x 256 c2, 512 threads, double-buffered K chunks of 64.
// ---------------------------------------------------------------------------
__global__ __launch_bounds__(512, 1)
void main_kernel(const float* __restrict__ bng, const float* __restrict__ bnb,
                 const float* __restrict__ bnm, const float* __restrict__ bnv,
                 float* __restrict__ out) {
    extern __shared__ char smem[];
    uint32_t sb = smem_u32(smem);
    int t = threadIdx.x, wid = t >> 5, lid = t & 31;
    int b = blockIdx.y;
    int p0 = blockIdx.x * TPIX;

    if (t < 256) {
        float sc = bng[t] * rsqrtf(bnv[t] + 1e-5f);
        ((float*)(smem + SM_BN))[t]       = sc;
        ((float*)(smem + SM_BN))[256 + t] = bnb[t] - bnm[t] * sc;
    }

    int pix = t & 127;          // gather: pixel
    int kg  = t >> 7;           // gather: 8-pair group (0..3)
    int wm  = wid & 3;
    int wn  = wid >> 2;
    const uint32_t* x2b = g_x2 + (size_t)b * 64 * P_;

    float acc[2][8][4];
#pragma unroll
    for (int mt = 0; mt < 2; mt++)
#pragma unroll
        for (int nt = 0; nt < 8; nt++)
#pragma unroll
            for (int j = 0; j < 4; j++) acc[mt][nt][j] = 0.f;

    // ---- prologue: stage chunk 0 into stage 0 ----
    {
        const uint4* src = (const uint4*)g_wh;
#pragma unroll
        for (int i = 0; i < 4; i++) {
            int u = i * 512 + t;
            *(uint4*)(smem + SM_ST + A_BYTES + (u >> 3) * BPITCH + (u & 7) * 16) =
                __ldg(src + u);
        }
        int gi = b * NPT * P_ + p0 + pix;
        int4   id  = __ldg(&g_idx[gi]);
        float4 gwv = __ldg(&g_gw[gi]);
        const uint32_t* xc = x2b + (size_t)(kg * 8) * P_;
#pragma unroll
        for (int i = 0; i < 8; i++) {
            const uint32_t* xp = xc + (size_t)i * P_;
            float2 f0 = up2(__ldg(xp + id.x));
            float2 f1 = up2(__ldg(xp + id.y));
            float2 f2 = up2(__ldg(xp + id.z));
            float2 f3 = up2(__ldg(xp + id.w));
            float v0 = gwv.x * f0.x + gwv.y * f1.x + gwv.z * f2.x + gwv.w * f3.x;
            float v1 = gwv.x * f0.y + gwv.y * f1.y + gwv.z * f2.y + gwv.w * f3.y;
            unsigned h; CVT2H(h, v0, v1);
            *(unsigned*)(smem + SM_ST + (uint32_t)pix * APITCH + kg * 32 + i * 4) = h;
        }
    }
    __syncthreads();

#pragma unroll 1
    for (int c = 0; c < NCHUNK; c++) {
        int st = c & 1;
        uint32_t sA  = sb + SM_ST + st * STG;
        uint32_t sBB = sA + A_BYTES;
        uint32_t nA  = SM_ST + (st ^ 1) * STG;
        bool pf = (c < NCHUNK - 1);
        int cn = c + 1;

        // prefetch next B tile + bilinear params; preload pair 0 corners
        uint4 breg[4];
        int4 id; float4 gwv;
        const uint32_t* xc = x2b;
        uint32_t ub[2][4];
        if (pf) {
            const uint4* src = (const uint4*)(g_wh + cn * C2 * KCH);
#pragma unroll
            for (int i = 0; i < 4; i++) breg[i] = __ldg(src + i * 512 + t);
            int gi = (b * NPT + (cn >> 1)) * P_ + p0 + pix;
            id  = __ldg(&g_idx[gi]);
            gwv = __ldg(&g_gw[gi]);
            xc = x2b + (size_t)((cn & 1) * 32 + kg * 8) * P_;
            ub[0][0] = __ldg(xc + id.x); ub[0][1] = __ldg(xc + id.y);
            ub[0][2] = __ldg(xc + id.z); ub[0][3] = __ldg(xc + id.w);
        }

        uint32_t aA = sA + (wm * 32 + (lid & 15)) * APITCH + (lid >> 4) * 16;
        uint32_t aB = sBB + (wn * 64 + (lid & 7) + (lid >> 4) * 8) * BPITCH
                    + ((lid >> 3) & 1) * 16;
        uint32_t dA = nA + (uint32_t)pix * APITCH + kg * 32;

        uint32_t ah[2][4];
#pragma unroll
        for (int s = 0; s < 8; s++) {
            int ks = s >> 1, gp = s & 1;

            // issue corner loads for pair s+1 (consumed next iteration)
            if (pf && s < 7) {
                const uint32_t* xp = xc + (size_t)(s + 1) * P_;
                uint32_t* un = ub[(s + 1) & 1];
                un[0] = __ldg(xp + id.x); un[1] = __ldg(xp + id.y);
                un[2] = __ldg(xp + id.z); un[3] = __ldg(xp + id.w);
            }

            if (gp == 0) {
                ldsm4(ah[0], aA + ks * 32);
                ldsm4(ah[1], aA + 16 * APITCH + ks * 32);
            }

#pragma unroll
            for (int g2 = 0; g2 < 2; g2++) {
                int g = gp * 2 + g2;
                uint32_t bf[4];
                ldsm4(bf, aB + g * 16 * BPITCH + ks * 32);
#pragma unroll
                for (int mt = 0; mt < 2; mt++) {
                    mma16816(acc[mt][2 * g],     ah[mt], bf);
                    mma16816(acc[mt][2 * g + 1], ah[mt], bf + 2);
                }
            }

            // combine + convert + store pair s (loaded last iteration)
            if (pf) {
                const uint32_t* us = ub[s & 1];
                float2 f0 = up2(us[0]), f1 = up2(us[1]);
                float2 f2 = up2(us[2]), f3 = up2(us[3]);
                float v0 = gwv.x * f0.x + gwv.y * f1.x + gwv.z * f2.x + gwv.w * f3.x;
                float v1 = gwv.x * f0.y + gwv.y * f1.y + gwv.z * f2.y + gwv.w * f3.y;
                unsigned h; CVT2H(h, v0, v1);
                *(unsigned*)(smem + dA + s * 4) = h;
            }
        }

        if (pf) {
#pragma unroll
            for (int i = 0; i < 4; i++) {
                int u = i * 512 + t;
                *(uint4*)(smem + nA + A_BYTES + (u >> 3) * BPITCH + (u & 7) * 16) =
                    breg[i];
            }
        }
        __syncthreads();
    }

    // ---- epilogue: BN + SiLU via SMEM transpose, coalesced out ----
    const float* scs = (const float*)(smem + SM_BN);
    const float* shs = scs + 256;
    float* sO = (float*)(smem + SM_ST);
#pragma unroll
    for (int half = 0; half < 2; half++) {
        if ((wn >> 1) == half) {
#pragma unroll
            for (int mt = 0; mt < 2; mt++)
#pragma unroll
                for (int nt = 0; nt < 8; nt++)
#pragma unroll
                    for (int j = 0; j < 4; j++) {
                        int row = wm * 32 + mt * 16 + (lid >> 2) + 8 * (j >> 1);
                        int col = (wn & 1) * 64 + nt * 8 + 2 * (lid & 3) + (j & 1);
                        sO[col * OPITCH + row] = acc[mt][nt][j];
                    }
        }
        __syncthreads();
#pragma unroll
        for (int it = 0; it < 32; it++) {
            int idx = it * 512 + t;
            int c2l = idx >> 7, pp = idx & 127;
            int c2 = half * 128 + c2l;
            float v = sO[c2l * OPITCH + pp] * scs[c2] + shs[c2];
            out[((size_t)b * C2 + c2) * P_ + p0 + pp] = v / (1.f + __expf(-v));
        }
        __syncthreads();
    }
}

// ---------------------------------------------------------------------------
extern "C" void kernel_launch(void* const* d_in, const int* in_sizes, int n_in,
                              void* d_out, int out_size) {
    const float* x   = (const float*)d_in[0];
    const float* pw  = (const float*)d_in[1];
    const float* pb  = (const float*)d_in[2];
    const float* cw  = (const float*)d_in[3];
    const float* bng = (const float*)d_in[4];
    const float* bnb = (const float*)d_in[5];
    const float* bnm = (const float*)d_in[6];
    const float* bnv = (const float*)d_in[7];
    float* out = (float*)d_out;

    cudaFuncSetAttribute(offset_kernel, cudaFuncAttributeMaxDynamicSharedMemorySize, 55296);
    cudaFuncSetAttribute(main_kernel,   cudaFuncAttributeMaxDynamicSharedMemorySize, SM_TOTAL);

    prep_kernel<<<(NCHUNK * C2 * KCH + 255) / 256, 256>>>(cw, pw);
    offset_kernel<<<B_ * P_ / 256, 256, 55296>>>(x, pb);
    dim3 g2(P_ / TPIX, B_);
    main_kernel<<<g2, 512, SM_TOTAL>>>(bng, bnb, bnm, bnv, out);
}